// round 14
// baseline (speedup 1.0000x reference)
#include <cuda_runtime.h>
#include <cuda_fp16.h>

#define N_NODES 20000
#define EDGES   640000
#define C       256

// ---------------- scratch ----------------
__device__ __half g_hA[N_NODES * C];    // x_norm fp16, later hop2 output (GEMM A)
__device__ __half g_hB[N_NODES * C];    // hop1 output fp16
__device__ __half g_hW[C * C];          // fp16 weights [n][k]
__device__ unsigned long long g_pk[N_NODES];  // (cnt<<32) | deg_fix20  -- self-cleaned
__device__ float  g_deg[N_NODES];       // deg^-1/2
__device__ int    g_ptr[N_NODES + 1];
__device__ int    g_cursor[N_NODES];
__device__ __align__(16) int2   g_rc[EDGES];    // packed (row, col)
__device__ __align__(16) float2 g_edge[EDGES];  // packed (srcidx-as-bits, wval)

// ---------------- setup kernels ----------------

// fused launch phase A:
//   blocks [0, NB_EXT)      : dtype detect + index materialization (2 edges/thr,
//                             vectorized int64 loads) + packed degree atomics
//   blocks [NB_EXT, +2500)  : L2-normalize x -> g_hA (warp/row)
#define NB_EXT 1250
__global__ void extract_norm_kernel(const void* ei, const float* __restrict__ w,
                                    const float* __restrict__ x) {
    int b = blockIdx.x;
    if (b < NB_EXT) {
        __shared__ int s_bad;
        if (threadIdx.x == 0) s_bad = 0;
        __syncthreads();
        {
            const long long* p = (const long long*)ei;
            if (threadIdx.x < 128) {
                long long v = p[threadIdx.x];
                if (v < 0 || v >= N_NODES) s_bad = 1;
            }
        }
        __syncthreads();
        int is64 = !s_bad;

        int e = (b * 256 + threadIdx.x) * 2;   // 2 edges per thread
        long long r0, c0, r1, c1;
        if (is64) {
            longlong2 rr = *reinterpret_cast<const longlong2*>((const long long*)ei + e);
            longlong2 cc = *reinterpret_cast<const longlong2*>((const long long*)ei + EDGES + e);
            r0 = rr.x; r1 = rr.y; c0 = cc.x; c1 = cc.y;
        } else {
            int2 rr = *reinterpret_cast<const int2*>((const int*)ei + e);
            int2 cc = *reinterpret_cast<const int2*>((const int*)ei + EDGES + e);
            r0 = rr.x; r1 = rr.y; c0 = cc.x; c1 = cc.y;
        }
        if (r0 < 0 || r0 >= N_NODES) r0 = 0;
        if (c0 < 0 || c0 >= N_NODES) c0 = 0;
        if (r1 < 0 || r1 >= N_NODES) r1 = 0;
        if (c1 < 0 || c1 >= N_NODES) c1 = 0;
        *reinterpret_cast<int4*>(&g_rc[e]) =
            make_int4((int)r0, (int)c0, (int)r1, (int)c1);
        float2 w2 = *reinterpret_cast<const float2*>(&w[e]);
        unsigned wf0 = (unsigned)(w2.x * 1048576.0f + 0.5f);
        unsigned wf1 = (unsigned)(w2.y * 1048576.0f + 0.5f);
        atomicAdd(&g_pk[c0], (1ULL << 32) | (unsigned long long)wf0);
        atomicAdd(&g_pk[c1], (1ULL << 32) | (unsigned long long)wf1);
        return;
    }
    b -= NB_EXT;
    int warp = (b * 256 + threadIdx.x) >> 5;
    int lane = threadIdx.x & 31;
    if (warp >= N_NODES) return;
    const float4* xr = reinterpret_cast<const float4*>(x + (size_t)warp * C);
    float4 v0 = xr[lane * 2];
    float4 v1 = xr[lane * 2 + 1];
    float ss = v0.x*v0.x + v0.y*v0.y + v0.z*v0.z + v0.w*v0.w
             + v1.x*v1.x + v1.y*v1.y + v1.z*v1.z + v1.w*v1.w;
    #pragma unroll
    for (int o = 16; o; o >>= 1) ss += __shfl_xor_sync(0xffffffffu, ss, o);
    float inv = 1.0f / fmaxf(sqrtf(ss), 1e-12f);
    __half2 h[4];
    h[0] = __floats2half2_rn(v0.x * inv, v0.y * inv);
    h[1] = __floats2half2_rn(v0.z * inv, v0.w * inv);
    h[2] = __floats2half2_rn(v1.x * inv, v1.y * inv);
    h[3] = __floats2half2_rn(v1.z * inv, v1.w * inv);
    *reinterpret_cast<uint4*>(g_hA + (size_t)warp * C + lane * 8) =
        *reinterpret_cast<uint4*>(h);
}

// scan: unpack g_pk -> dis + counts, self-clean g_pk, exclusive scan -> ptr/cursor.
__global__ void scan_kernel() {
    __shared__ int wsum[32];
    __shared__ int s_running;
    int tid = threadIdx.x;                 // 1024 threads
    int lane = tid & 31, wid = tid >> 5;
    if (tid == 0) s_running = 0;
    __syncthreads();

    const int NV = N_NODES / 4;            // 5000 groups of 4 nodes
    for (int base = 0; base < NV; base += 1024) {
        int iv = base + tid;
        int c4[4] = {0, 0, 0, 0};
        if (iv < NV) {
            ulonglong2 p0 = reinterpret_cast<const ulonglong2*>(g_pk)[iv * 2];
            ulonglong2 p1 = reinterpret_cast<const ulonglong2*>(g_pk)[iv * 2 + 1];
            reinterpret_cast<ulonglong2*>(g_pk)[iv * 2]     = make_ulonglong2(0ULL, 0ULL);
            reinterpret_cast<ulonglong2*>(g_pk)[iv * 2 + 1] = make_ulonglong2(0ULL, 0ULL);
            c4[0] = (int)(p0.x >> 32); c4[1] = (int)(p0.y >> 32);
            c4[2] = (int)(p1.x >> 32); c4[3] = (int)(p1.y >> 32);
            const float S = 1.0f / 1048576.0f;
            float d0 = (float)(unsigned)(p0.x & 0xffffffffULL) * S;
            float d1 = (float)(unsigned)(p0.y & 0xffffffffULL) * S;
            float d2 = (float)(unsigned)(p1.x & 0xffffffffULL) * S;
            float d3 = (float)(unsigned)(p1.y & 0xffffffffULL) * S;
            float4 dis;
            dis.x = (d0 > 0.0f) ? rsqrtf(d0) : 0.0f;
            dis.y = (d1 > 0.0f) ? rsqrtf(d1) : 0.0f;
            dis.z = (d2 > 0.0f) ? rsqrtf(d2) : 0.0f;
            dis.w = (d3 > 0.0f) ? rsqrtf(d3) : 0.0f;
            reinterpret_cast<float4*>(g_deg)[iv] = dis;
        }
        int lsum = c4[0] + c4[1] + c4[2] + c4[3];
        int s = lsum;
        #pragma unroll
        for (int o = 1; o < 32; o <<= 1) {
            int t = __shfl_up_sync(0xffffffffu, s, o);
            if (lane >= o) s += t;
        }
        if (lane == 31) wsum[wid] = s;
        __syncthreads();
        if (wid == 0) {
            int ws = wsum[lane];
            #pragma unroll
            for (int o = 1; o < 32; o <<= 1) {
                int t = __shfl_up_sync(0xffffffffu, ws, o);
                if (lane >= o) ws += t;
            }
            wsum[lane] = ws;
        }
        __syncthreads();
        int excl = s_running + s - lsum + (wid > 0 ? wsum[wid - 1] : 0);
        if (iv < NV) {
            int4 p;
            p.x = excl;
            p.y = p.x + c4[0];
            p.z = p.y + c4[1];
            p.w = p.z + c4[2];
            reinterpret_cast<int4*>(g_ptr)[iv]    = p;
            reinterpret_cast<int4*>(g_cursor)[iv] = p;
        }
        __syncthreads();
        if (tid == 0) s_running += wsum[31];
        __syncthreads();
    }
    if (tid == 0) g_ptr[N_NODES] = s_running;
}

// fused launch phase B:
//   blocks [0, NB_FILL4)        : CSR fill, 4 edges/thread (deeper atomic/store MLP)
//   blocks [NB_FILL4, +32)      : W -> fp16
#define NB_FILL4 625
__global__ void fill_convw_kernel(const float* __restrict__ w,
                                  const float* __restrict__ W) {
    int b = blockIdx.x;
    if (b < NB_FILL4) {
        int e = (b * 256 + threadIdx.x) * 4;
        int4 rcA = *reinterpret_cast<const int4*>(&g_rc[e]);       // (r0,c0,r1,c1)
        int4 rcB = *reinterpret_cast<const int4*>(&g_rc[e + 2]);   // (r2,c2,r3,c3)
        float4 w4 = *reinterpret_cast<const float4*>(&w[e]);
        int pos0 = atomicAdd(&g_cursor[rcA.y], 1);
        int pos1 = atomicAdd(&g_cursor[rcA.w], 1);
        int pos2 = atomicAdd(&g_cursor[rcB.y], 1);
        int pos3 = atomicAdd(&g_cursor[rcB.w], 1);
        float wv0 = g_deg[rcA.x] * w4.x * g_deg[rcA.y];
        float wv1 = g_deg[rcA.z] * w4.y * g_deg[rcA.w];
        float wv2 = g_deg[rcB.x] * w4.z * g_deg[rcB.y];
        float wv3 = g_deg[rcB.z] * w4.w * g_deg[rcB.w];
        g_edge[pos0] = make_float2(__int_as_float(rcA.x), wv0);
        g_edge[pos1] = make_float2(__int_as_float(rcA.z), wv1);
        g_edge[pos2] = make_float2(__int_as_float(rcB.x), wv2);
        g_edge[pos3] = make_float2(__int_as_float(rcB.z), wv3);
        return;
    }
    int i = ((b - NB_FILL4) * 256 + threadIdx.x) * 8;
    if (i < C * C) {
        __half2 h[4];
        #pragma unroll
        for (int k = 0; k < 4; k++)
            h[k] = __floats2half2_rn(W[i + 2*k], W[i + 2*k + 1]);
        *reinterpret_cast<uint4*>(g_hW + i) = *reinterpret_cast<uint4*>(h);
    }
}

// warp per target node: fp16 src rows, fp32 accumulate, fp16 out.
__global__ void __launch_bounds__(256, 8)
gather_kernel(const __half* __restrict__ src, __half* __restrict__ dst) {
    int node = (blockIdx.x * blockDim.x + threadIdx.x) >> 5;
    int lane = threadIdx.x & 31;
    if (node >= N_NODES) return;
    int i   = g_ptr[node];
    int end = g_ptr[node + 1];
    float acc[8] = {};

    if ((i & 1) && i < end) {
        float2 me = g_edge[i];
        int r = __float_as_int(me.x);
        float wv = me.y;
        uint4 v = *reinterpret_cast<const uint4*>(src + (size_t)r * C + lane * 8);
        const __half2* h = reinterpret_cast<const __half2*>(&v);
        #pragma unroll
        for (int k = 0; k < 4; k++) {
            float2 f = __half22float2(h[k]);
            acc[2*k]   += wv * f.x;
            acc[2*k+1] += wv * f.y;
        }
        i++;
    }

    for (; i + 8 <= end; i += 8) {
        uint4 m[4];
        #pragma unroll
        for (int j = 0; j < 4; j++)
            m[j] = *reinterpret_cast<const uint4*>(&g_edge[i + 2 * j]);
        int r[8]; float wv[8];
        #pragma unroll
        for (int j = 0; j < 4; j++) {
            r[2*j]   = (int)m[j].x;  wv[2*j]   = __uint_as_float(m[j].y);
            r[2*j+1] = (int)m[j].z;  wv[2*j+1] = __uint_as_float(m[j].w);
        }
        uint4 v[8];
        #pragma unroll
        for (int u = 0; u < 8; u++)
            v[u] = *reinterpret_cast<const uint4*>(src + (size_t)r[u] * C + lane * 8);
        #pragma unroll
        for (int u = 0; u < 8; u++) {
            const __half2* h = reinterpret_cast<const __half2*>(&v[u]);
            #pragma unroll
            for (int k = 0; k < 4; k++) {
                float2 f = __half22float2(h[k]);
                acc[2*k]   += wv[u] * f.x;
                acc[2*k+1] += wv[u] * f.y;
            }
        }
    }
    for (; i < end; i++) {
        float2 me = g_edge[i];
        int r = __float_as_int(me.x);
        float wv = me.y;
        uint4 v = *reinterpret_cast<const uint4*>(src + (size_t)r * C + lane * 8);
        const __half2* h = reinterpret_cast<const __half2*>(&v);
        #pragma unroll
        for (int k = 0; k < 4; k++) {
            float2 f = __half22float2(h[k]);
            acc[2*k]   += wv * f.x;
            acc[2*k+1] += wv * f.y;
        }
    }

    __half2 h[4];
    #pragma unroll
    for (int k = 0; k < 4; k++) h[k] = __floats2half2_rn(acc[2*k], acc[2*k+1]);
    *reinterpret_cast<uint4*>(dst + (size_t)node * C + lane * 8) =
        *reinterpret_cast<uint4*>(h);
}

// ---------------- tensor-core GEMM (register double-buffered) ----------------
#define BK 64

__global__ void hgemm_kernel(const __half* __restrict__ A,
                             const float* __restrict__ bias,
                             float* __restrict__ out) {
    __shared__ __half As[128 * BK];
    __shared__ __half Bs[64 * BK];

    int tid = threadIdx.x;
    int lane = tid & 31;
    int warp = tid >> 5;
    int wm = warp & 3;
    int wn = warp >> 2;
    int g  = lane >> 2;
    int tg = lane & 3;

    int m0 = blockIdx.x * 128;
    int n0 = blockIdx.y * 64;

    float d[2][4][4] = {};
    uint4 pa[4], pb[2];

    #pragma unroll
    for (int i = 0; i < 4; i++) {
        int lin = tid + i * 256;
        int row = lin >> 3;
        int ch  = lin & 7;
        int gm  = m0 + row;
        pa[i] = make_uint4(0, 0, 0, 0);
        if (gm < N_NODES)
            pa[i] = *reinterpret_cast<const uint4*>(A + (size_t)gm * C + ch * 8);
    }
    #pragma unroll
    for (int i = 0; i < 2; i++) {
        int lin = tid + i * 256;
        int row = lin >> 3;
        int ch  = lin & 7;
        pb[i] = *reinterpret_cast<const uint4*>(g_hW + (size_t)(n0 + row) * C + ch * 8);
    }

    #pragma unroll
    for (int ks = 0; ks < C / BK; ks++) {
        #pragma unroll
        for (int i = 0; i < 4; i++) {
            int lin = tid + i * 256;
            int row = lin >> 3;
            int ch  = lin & 7;
            *reinterpret_cast<uint4*>(&As[row * BK + ((ch ^ (row & 7)) * 8)]) = pa[i];
        }
        #pragma unroll
        for (int i = 0; i < 2; i++) {
            int lin = tid + i * 256;
            int row = lin >> 3;
            int ch  = lin & 7;
            *reinterpret_cast<uint4*>(&Bs[row * BK + ((ch ^ (row & 7)) * 8)]) = pb[i];
        }
        __syncthreads();

        if (ks + 1 < C / BK) {
            int k0 = (ks + 1) * BK;
            #pragma unroll
            for (int i = 0; i < 4; i++) {
                int lin = tid + i * 256;
                int row = lin >> 3;
                int ch  = lin & 7;
                int gm  = m0 + row;
                pa[i] = make_uint4(0, 0, 0, 0);
                if (gm < N_NODES)
                    pa[i] = *reinterpret_cast<const uint4*>(A + (size_t)gm * C + k0 + ch * 8);
            }
            #pragma unroll
            for (int i = 0; i < 2; i++) {
                int lin = tid + i * 256;
                int row = lin >> 3;
                int ch  = lin & 7;
                pb[i] = *reinterpret_cast<const uint4*>(g_hW + (size_t)(n0 + row) * C + k0 + ch * 8);
            }
        }

        #pragma unroll
        for (int kc = 0; kc < BK / 16; kc++) {
            unsigned a[2][4];
            #pragma unroll
            for (int sm = 0; sm < 2; sm++) {
                int r0 = wm * 32 + sm * 16 + g;
                int r1 = r0 + 8;
                a[sm][0] = *reinterpret_cast<const unsigned*>(&As[r0 * BK + (((kc * 2)     ^ (r0 & 7)) * 8) + tg * 2]);
                a[sm][1] = *reinterpret_cast<const unsigned*>(&As[r1 * BK + (((kc * 2)     ^ (r1 & 7)) * 8) + tg * 2]);
                a[sm][2] = *reinterpret_cast<const unsigned*>(&As[r0 * BK + (((kc * 2 + 1) ^ (r0 & 7)) * 8) + tg * 2]);
                a[sm][3] = *reinterpret_cast<const unsigned*>(&As[r1 * BK + (((kc * 2 + 1) ^ (r1 & 7)) * 8) + tg * 2]);
            }
            #pragma unroll
            for (int sn = 0; sn < 4; sn++) {
                int nr = wn * 32 + sn * 8 + g;
                unsigned b0 = *reinterpret_cast<const unsigned*>(&Bs[nr * BK + (((kc * 2)     ^ (nr & 7)) * 8) + tg * 2]);
                unsigned b1 = *reinterpret_cast<const unsigned*>(&Bs[nr * BK + (((kc * 2 + 1) ^ (nr & 7)) * 8) + tg * 2]);
                #pragma unroll
                for (int sm = 0; sm < 2; sm++) {
                    asm volatile(
                        "mma.sync.aligned.m16n8k16.row.col.f32.f16.f16.f32 "
                        "{%0,%1,%2,%3}, {%4,%5,%6,%7}, {%8,%9}, {%0,%1,%2,%3};"
                        : "+f"(d[sm][sn][0]), "+f"(d[sm][sn][1]),
                          "+f"(d[sm][sn][2]), "+f"(d[sm][sn][3])
                        : "r"(a[sm][0]), "r"(a[sm][1]), "r"(a[sm][2]), "r"(a[sm][3]),
                          "r"(b0), "r"(b1));
                }
            }
        }
        __syncthreads();
    }

    #pragma unroll
    for (int sm = 0; sm < 2; sm++) {
        #pragma unroll
        for (int sn = 0; sn < 4; sn++) {
            int col = n0 + wn * 32 + sn * 8 + tg * 2;
            float b0 = bias[col], b1 = bias[col + 1];
            int r0 = m0 + wm * 32 + sm * 16 + g;
            if (r0 < N_NODES) {
                float2 v = make_float2(d[sm][sn][0] + b0, d[sm][sn][1] + b1);
                *reinterpret_cast<float2*>(out + (size_t)r0 * C + col) = v;
            }
            int r1 = r0 + 8;
            if (r1 < N_NODES) {
                float2 v = make_float2(d[sm][sn][2] + b0, d[sm][sn][3] + b1);
                *reinterpret_cast<float2*>(out + (size_t)r1 * C + col) = v;
            }
        }
    }
}

// ---------------- launch ----------------

extern "C" void kernel_launch(void* const* d_in, const int* in_sizes, int n_in,
                              void* d_out, int out_size) {
    const float* x  = (const float*)d_in[0];
    const void*  ei = d_in[1];
    const float* w  = (const float*)d_in[2];
    const float* lw = (const float*)d_in[3];
    const float* lb = (const float*)d_in[4];
    float* out = (float*)d_out;

    __half *hA, *hB;
    cudaGetSymbolAddress((void**)&hA, g_hA);
    cudaGetSymbolAddress((void**)&hB, g_hB);

    const int T = 256;

    // CSR build + feature prep (3 launches)
    extract_norm_kernel<<<NB_EXT + 2500, T>>>(ei, w, x);
    scan_kernel<<<1, 1024>>>();
    fill_convw_kernel<<<NB_FILL4 + 32, T>>>(w, lw);

    // hops: hA -> hB -> hA
    int ggrid = (N_NODES * 32 + T - 1) / T;
    gather_kernel<<<ggrid, T>>>(hA, hB);
    gather_kernel<<<ggrid, T>>>(hB, hA);

    // tensor-core linear
    dim3 lgrid((N_NODES + 127) / 128, C / 64);
    hgemm_kernel<<<lgrid, T>>>(hA, lb, out);
}

// round 15
// speedup vs baseline: 1.4991x; 1.4991x over previous
#include <cuda_runtime.h>
#include <cuda_fp16.h>

#define N_NODES 20000
#define EDGES   640000
#define C       256

// ---------------- scratch ----------------
__device__ __half g_hA[N_NODES * C];    // x_norm fp16, later hop2 output (GEMM A)
__device__ __half g_hB[N_NODES * C];    // hop1 output fp16
__device__ __half g_hW[C * C];          // fp16 weights [n][k]
__device__ unsigned long long g_pk[N_NODES];  // (cnt<<32) | deg_fix20  -- self-cleaned
__device__ float  g_deg[N_NODES];       // deg^-1/2
__device__ int    g_ptr[N_NODES + 1];
__device__ int    g_cursor[N_NODES];
__device__ __align__(16) int2   g_rc[EDGES];    // packed (row, col)
__device__ __align__(16) float2 g_edge[EDGES];  // packed (srcidx-as-bits, wval)

// ---------------- setup kernels ----------------

// fused launch phase A:
//   blocks [0, NB_EXT)      : dtype detect + index materialization (2 edges/thr,
//                             vectorized int64 loads) + packed degree atomics
//   blocks [NB_EXT, +2500)  : L2-normalize x -> g_hA (warp/row)
#define NB_EXT 1250
__global__ void extract_norm_kernel(const void* ei, const float* __restrict__ w,
                                    const float* __restrict__ x) {
    int b = blockIdx.x;
    if (b < NB_EXT) {
        __shared__ int s_bad;
        if (threadIdx.x == 0) s_bad = 0;
        __syncthreads();
        {
            const long long* p = (const long long*)ei;
            if (threadIdx.x < 128) {
                long long v = p[threadIdx.x];
                if (v < 0 || v >= N_NODES) s_bad = 1;
            }
        }
        __syncthreads();
        int is64 = !s_bad;

        int e = (b * 256 + threadIdx.x) * 2;   // 2 edges per thread
        long long r0, c0, r1, c1;
        if (is64) {
            longlong2 rr = *reinterpret_cast<const longlong2*>((const long long*)ei + e);
            longlong2 cc = *reinterpret_cast<const longlong2*>((const long long*)ei + EDGES + e);
            r0 = rr.x; r1 = rr.y; c0 = cc.x; c1 = cc.y;
        } else {
            int2 rr = *reinterpret_cast<const int2*>((const int*)ei + e);
            int2 cc = *reinterpret_cast<const int2*>((const int*)ei + EDGES + e);
            r0 = rr.x; r1 = rr.y; c0 = cc.x; c1 = cc.y;
        }
        if (r0 < 0 || r0 >= N_NODES) r0 = 0;
        if (c0 < 0 || c0 >= N_NODES) c0 = 0;
        if (r1 < 0 || r1 >= N_NODES) r1 = 0;
        if (c1 < 0 || c1 >= N_NODES) c1 = 0;
        *reinterpret_cast<int4*>(&g_rc[e]) =
            make_int4((int)r0, (int)c0, (int)r1, (int)c1);
        float2 w2 = *reinterpret_cast<const float2*>(&w[e]);
        unsigned wf0 = (unsigned)(w2.x * 1048576.0f + 0.5f);
        unsigned wf1 = (unsigned)(w2.y * 1048576.0f + 0.5f);
        atomicAdd(&g_pk[c0], (1ULL << 32) | (unsigned long long)wf0);
        atomicAdd(&g_pk[c1], (1ULL << 32) | (unsigned long long)wf1);
        return;
    }
    b -= NB_EXT;
    int warp = (b * 256 + threadIdx.x) >> 5;
    int lane = threadIdx.x & 31;
    if (warp >= N_NODES) return;
    const float4* xr = reinterpret_cast<const float4*>(x + (size_t)warp * C);
    float4 v0 = xr[lane * 2];
    float4 v1 = xr[lane * 2 + 1];
    float ss = v0.x*v0.x + v0.y*v0.y + v0.z*v0.z + v0.w*v0.w
             + v1.x*v1.x + v1.y*v1.y + v1.z*v1.z + v1.w*v1.w;
    #pragma unroll
    for (int o = 16; o; o >>= 1) ss += __shfl_xor_sync(0xffffffffu, ss, o);
    float inv = 1.0f / fmaxf(sqrtf(ss), 1e-12f);
    __half2 h[4];
    h[0] = __floats2half2_rn(v0.x * inv, v0.y * inv);
    h[1] = __floats2half2_rn(v0.z * inv, v0.w * inv);
    h[2] = __floats2half2_rn(v1.x * inv, v1.y * inv);
    h[3] = __floats2half2_rn(v1.z * inv, v1.w * inv);
    *reinterpret_cast<uint4*>(g_hA + (size_t)warp * C + lane * 8) =
        *reinterpret_cast<uint4*>(h);
}

// scan: unpack g_pk -> dis + counts, self-clean g_pk, exclusive scan -> ptr/cursor.
__global__ void scan_kernel() {
    __shared__ int wsum[32];
    __shared__ int s_running;
    int tid = threadIdx.x;                 // 1024 threads
    int lane = tid & 31, wid = tid >> 5;
    if (tid == 0) s_running = 0;
    __syncthreads();

    const int NV = N_NODES / 4;            // 5000 groups of 4 nodes
    for (int base = 0; base < NV; base += 1024) {
        int iv = base + tid;
        int c4[4] = {0, 0, 0, 0};
        if (iv < NV) {
            ulonglong2 p0 = reinterpret_cast<const ulonglong2*>(g_pk)[iv * 2];
            ulonglong2 p1 = reinterpret_cast<const ulonglong2*>(g_pk)[iv * 2 + 1];
            reinterpret_cast<ulonglong2*>(g_pk)[iv * 2]     = make_ulonglong2(0ULL, 0ULL);
            reinterpret_cast<ulonglong2*>(g_pk)[iv * 2 + 1] = make_ulonglong2(0ULL, 0ULL);
            c4[0] = (int)(p0.x >> 32); c4[1] = (int)(p0.y >> 32);
            c4[2] = (int)(p1.x >> 32); c4[3] = (int)(p1.y >> 32);
            const float S = 1.0f / 1048576.0f;
            float d0 = (float)(unsigned)(p0.x & 0xffffffffULL) * S;
            float d1 = (float)(unsigned)(p0.y & 0xffffffffULL) * S;
            float d2 = (float)(unsigned)(p1.x & 0xffffffffULL) * S;
            float d3 = (float)(unsigned)(p1.y & 0xffffffffULL) * S;
            float4 dis;
            dis.x = (d0 > 0.0f) ? rsqrtf(d0) : 0.0f;
            dis.y = (d1 > 0.0f) ? rsqrtf(d1) : 0.0f;
            dis.z = (d2 > 0.0f) ? rsqrtf(d2) : 0.0f;
            dis.w = (d3 > 0.0f) ? rsqrtf(d3) : 0.0f;
            reinterpret_cast<float4*>(g_deg)[iv] = dis;
        }
        int lsum = c4[0] + c4[1] + c4[2] + c4[3];
        int s = lsum;
        #pragma unroll
        for (int o = 1; o < 32; o <<= 1) {
            int t = __shfl_up_sync(0xffffffffu, s, o);
            if (lane >= o) s += t;
        }
        if (lane == 31) wsum[wid] = s;
        __syncthreads();
        if (wid == 0) {
            int ws = wsum[lane];
            #pragma unroll
            for (int o = 1; o < 32; o <<= 1) {
                int t = __shfl_up_sync(0xffffffffu, ws, o);
                if (lane >= o) ws += t;
            }
            wsum[lane] = ws;
        }
        __syncthreads();
        int excl = s_running + s - lsum + (wid > 0 ? wsum[wid - 1] : 0);
        if (iv < NV) {
            int4 p;
            p.x = excl;
            p.y = p.x + c4[0];
            p.z = p.y + c4[1];
            p.w = p.z + c4[2];
            reinterpret_cast<int4*>(g_ptr)[iv]    = p;
            reinterpret_cast<int4*>(g_cursor)[iv] = p;
        }
        __syncthreads();
        if (tid == 0) s_running += wsum[31];
        __syncthreads();
    }
    if (tid == 0) g_ptr[N_NODES] = s_running;
}

// fused launch phase B:
//   blocks [0, NB_FILL2)        : CSR fill, 2 edges/thread
//   blocks [NB_FILL2, +32)      : W -> fp16
#define NB_FILL2 1250
__global__ void fill_convw_kernel(const float* __restrict__ w,
                                  const float* __restrict__ W) {
    int b = blockIdx.x;
    if (b < NB_FILL2) {
        int e = (b * 256 + threadIdx.x) * 2;
        int4 rc2 = *reinterpret_cast<const int4*>(&g_rc[e]);   // (r0,c0,r1,c1)
        float2 w2 = *reinterpret_cast<const float2*>(&w[e]);
        int pos0 = atomicAdd(&g_cursor[rc2.y], 1);
        int pos1 = atomicAdd(&g_cursor[rc2.w], 1);
        float wv0 = g_deg[rc2.x] * w2.x * g_deg[rc2.y];
        float wv1 = g_deg[rc2.z] * w2.y * g_deg[rc2.w];
        g_edge[pos0] = make_float2(__int_as_float(rc2.x), wv0);
        g_edge[pos1] = make_float2(__int_as_float(rc2.z), wv1);
        return;
    }
    int i = ((b - NB_FILL2) * 256 + threadIdx.x) * 8;
    if (i < C * C) {
        __half2 h[4];
        #pragma unroll
        for (int k = 0; k < 4; k++)
            h[k] = __floats2half2_rn(W[i + 2*k], W[i + 2*k + 1]);
        *reinterpret_cast<uint4*>(g_hW + i) = *reinterpret_cast<uint4*>(h);
    }
}

// warp per target node: fp16 src rows, fp32 accumulate, fp16 out.
__global__ void __launch_bounds__(256, 8)
gather_kernel(const __half* __restrict__ src, __half* __restrict__ dst) {
    int node = (blockIdx.x * blockDim.x + threadIdx.x) >> 5;
    int lane = threadIdx.x & 31;
    if (node >= N_NODES) return;
    int i   = g_ptr[node];
    int end = g_ptr[node + 1];
    float acc[8] = {};

    if ((i & 1) && i < end) {
        float2 me = g_edge[i];
        int r = __float_as_int(me.x);
        float wv = me.y;
        uint4 v = *reinterpret_cast<const uint4*>(src + (size_t)r * C + lane * 8);
        const __half2* h = reinterpret_cast<const __half2*>(&v);
        #pragma unroll
        for (int k = 0; k < 4; k++) {
            float2 f = __half22float2(h[k]);
            acc[2*k]   += wv * f.x;
            acc[2*k+1] += wv * f.y;
        }
        i++;
    }

    for (; i + 8 <= end; i += 8) {
        uint4 m[4];
        #pragma unroll
        for (int j = 0; j < 4; j++)
            m[j] = *reinterpret_cast<const uint4*>(&g_edge[i + 2 * j]);
        int r[8]; float wv[8];
        #pragma unroll
        for (int j = 0; j < 4; j++) {
            r[2*j]   = (int)m[j].x;  wv[2*j]   = __uint_as_float(m[j].y);
            r[2*j+1] = (int)m[j].z;  wv[2*j+1] = __uint_as_float(m[j].w);
        }
        uint4 v[8];
        #pragma unroll
        for (int u = 0; u < 8; u++)
            v[u] = *reinterpret_cast<const uint4*>(src + (size_t)r[u] * C + lane * 8);
        #pragma unroll
        for (int u = 0; u < 8; u++) {
            const __half2* h = reinterpret_cast<const __half2*>(&v[u]);
            #pragma unroll
            for (int k = 0; k < 4; k++) {
                float2 f = __half22float2(h[k]);
                acc[2*k]   += wv[u] * f.x;
                acc[2*k+1] += wv[u] * f.y;
            }
        }
    }
    for (; i < end; i++) {
        float2 me = g_edge[i];
        int r = __float_as_int(me.x);
        float wv = me.y;
        uint4 v = *reinterpret_cast<const uint4*>(src + (size_t)r * C + lane * 8);
        const __half2* h = reinterpret_cast<const __half2*>(&v);
        #pragma unroll
        for (int k = 0; k < 4; k++) {
            float2 f = __half22float2(h[k]);
            acc[2*k]   += wv * f.x;
            acc[2*k+1] += wv * f.y;
        }
    }

    __half2 h[4];
    #pragma unroll
    for (int k = 0; k < 4; k++) h[k] = __floats2half2_rn(acc[2*k], acc[2*k+1]);
    *reinterpret_cast<uint4*>(dst + (size_t)node * C + lane * 8) =
        *reinterpret_cast<uint4*>(h);
}

// ---------------- tensor-core GEMM (register double-buffered) ----------------
#define BK 64

__global__ void hgemm_kernel(const __half* __restrict__ A,
                             const float* __restrict__ bias,
                             float* __restrict__ out) {
    __shared__ __half As[128 * BK];
    __shared__ __half Bs[64 * BK];

    int tid = threadIdx.x;
    int lane = tid & 31;
    int warp = tid >> 5;
    int wm = warp & 3;
    int wn = warp >> 2;
    int g  = lane >> 2;
    int tg = lane & 3;

    int m0 = blockIdx.x * 128;
    int n0 = blockIdx.y * 64;

    float d[2][4][4] = {};
    uint4 pa[4], pb[2];

    #pragma unroll
    for (int i = 0; i < 4; i++) {
        int lin = tid + i * 256;
        int row = lin >> 3;
        int ch  = lin & 7;
        int gm  = m0 + row;
        pa[i] = make_uint4(0, 0, 0, 0);
        if (gm < N_NODES)
            pa[i] = *reinterpret_cast<const uint4*>(A + (size_t)gm * C + ch * 8);
    }
    #pragma unroll
    for (int i = 0; i < 2; i++) {
        int lin = tid + i * 256;
        int row = lin >> 3;
        int ch  = lin & 7;
        pb[i] = *reinterpret_cast<const uint4*>(g_hW + (size_t)(n0 + row) * C + ch * 8);
    }

    #pragma unroll
    for (int ks = 0; ks < C / BK; ks++) {
        #pragma unroll
        for (int i = 0; i < 4; i++) {
            int lin = tid + i * 256;
            int row = lin >> 3;
            int ch  = lin & 7;
            *reinterpret_cast<uint4*>(&As[row * BK + ((ch ^ (row & 7)) * 8)]) = pa[i];
        }
        #pragma unroll
        for (int i = 0; i < 2; i++) {
            int lin = tid + i * 256;
            int row = lin >> 3;
            int ch  = lin & 7;
            *reinterpret_cast<uint4*>(&Bs[row * BK + ((ch ^ (row & 7)) * 8)]) = pb[i];
        }
        __syncthreads();

        if (ks + 1 < C / BK) {
            int k0 = (ks + 1) * BK;
            #pragma unroll
            for (int i = 0; i < 4; i++) {
                int lin = tid + i * 256;
                int row = lin >> 3;
                int ch  = lin & 7;
                int gm  = m0 + row;
                pa[i] = make_uint4(0, 0, 0, 0);
                if (gm < N_NODES)
                    pa[i] = *reinterpret_cast<const uint4*>(A + (size_t)gm * C + k0 + ch * 8);
            }
            #pragma unroll
            for (int i = 0; i < 2; i++) {
                int lin = tid + i * 256;
                int row = lin >> 3;
                int ch  = lin & 7;
                pb[i] = *reinterpret_cast<const uint4*>(g_hW + (size_t)(n0 + row) * C + k0 + ch * 8);
            }
        }

        #pragma unroll
        for (int kc = 0; kc < BK / 16; kc++) {
            unsigned a[2][4];
            #pragma unroll
            for (int sm = 0; sm < 2; sm++) {
                int r0 = wm * 32 + sm * 16 + g;
                int r1 = r0 + 8;
                a[sm][0] = *reinterpret_cast<const unsigned*>(&As[r0 * BK + (((kc * 2)     ^ (r0 & 7)) * 8) + tg * 2]);
                a[sm][1] = *reinterpret_cast<const unsigned*>(&As[r1 * BK + (((kc * 2)     ^ (r1 & 7)) * 8) + tg * 2]);
                a[sm][2] = *reinterpret_cast<const unsigned*>(&As[r0 * BK + (((kc * 2 + 1) ^ (r0 & 7)) * 8) + tg * 2]);
                a[sm][3] = *reinterpret_cast<const unsigned*>(&As[r1 * BK + (((kc * 2 + 1) ^ (r1 & 7)) * 8) + tg * 2]);
            }
            #pragma unroll
            for (int sn = 0; sn < 4; sn++) {
                int nr = wn * 32 + sn * 8 + g;
                unsigned b0 = *reinterpret_cast<const unsigned*>(&Bs[nr * BK + (((kc * 2)     ^ (nr & 7)) * 8) + tg * 2]);
                unsigned b1 = *reinterpret_cast<const unsigned*>(&Bs[nr * BK + (((kc * 2 + 1) ^ (nr & 7)) * 8) + tg * 2]);
                #pragma unroll
                for (int sm = 0; sm < 2; sm++) {
                    asm volatile(
                        "mma.sync.aligned.m16n8k16.row.col.f32.f16.f16.f32 "
                        "{%0,%1,%2,%3}, {%4,%5,%6,%7}, {%8,%9}, {%0,%1,%2,%3};"
                        : "+f"(d[sm][sn][0]), "+f"(d[sm][sn][1]),
                          "+f"(d[sm][sn][2]), "+f"(d[sm][sn][3])
                        : "r"(a[sm][0]), "r"(a[sm][1]), "r"(a[sm][2]), "r"(a[sm][3]),
                          "r"(b0), "r"(b1));
                }
            }
        }
        __syncthreads();
    }

    #pragma unroll
    for (int sm = 0; sm < 2; sm++) {
        #pragma unroll
        for (int sn = 0; sn < 4; sn++) {
            int col = n0 + wn * 32 + sn * 8 + tg * 2;
            float b0 = bias[col], b1 = bias[col + 1];
            int r0 = m0 + wm * 32 + sm * 16 + g;
            if (r0 < N_NODES) {
                float2 v = make_float2(d[sm][sn][0] + b0, d[sm][sn][1] + b1);
                *reinterpret_cast<float2*>(out + (size_t)r0 * C + col) = v;
            }
            int r1 = r0 + 8;
            if (r1 < N_NODES) {
                float2 v = make_float2(d[sm][sn][2] + b0, d[sm][sn][3] + b1);
                *reinterpret_cast<float2*>(out + (size_t)r1 * C + col) = v;
            }
        }
    }
}

// ---------------- launch ----------------

extern "C" void kernel_launch(void* const* d_in, const int* in_sizes, int n_in,
                              void* d_out, int out_size) {
    const float* x  = (const float*)d_in[0];
    const void*  ei = d_in[1];
    const float* w  = (const float*)d_in[2];
    const float* lw = (const float*)d_in[3];
    const float* lb = (const float*)d_in[4];
    float* out = (float*)d_out;

    __half *hA, *hB;
    cudaGetSymbolAddress((void**)&hA, g_hA);
    cudaGetSymbolAddress((void**)&hB, g_hB);

    const int T = 256;

    // CSR build + feature prep (3 launches)
    extract_norm_kernel<<<NB_EXT + 2500, T>>>(ei, w, x);
    scan_kernel<<<1, 1024>>>();
    fill_convw_kernel<<<NB_FILL2 + 32, T>>>(w, lw);

    // hops: hA -> hB -> hA
    int ggrid = (N_NODES * 32 + T - 1) / T;
    gather_kernel<<<ggrid, T>>>(hA, hB);
    gather_kernel<<<ggrid, T>>>(hB, hA);

    // tensor-core linear
    dim3 lgrid((N_NODES + 127) / 128, C / 64);
    hgemm_kernel<<<lgrid, T>>>(hA, lb, out);
}